// round 2
// baseline (speedup 1.0000x reference)
#include <cuda_runtime.h>

#define BB 64
#define SS 8192
#define DDIM 64
#define SPLIT 8
#define ROWS_P1 (SS / SPLIT)   // 1024 rows per phase-1 block

// ---------------- scratch (no allocations allowed) ----------------
__device__ float g_part[SPLIT * BB * DDIM * DDIM];   // 8 MB
__device__ float g_ksum_part[SPLIT * BB * DDIM];
__device__ float g_kv[BB * DDIM * DDIM];             // 1 MB
__device__ float g_ksum[BB * DDIM];

// ---------------- helpers ----------------
__device__ __forceinline__ unsigned long long ffma2(unsigned long long a,
                                                    unsigned long long b,
                                                    unsigned long long c) {
    unsigned long long d;
    asm("fma.rn.f32x2 %0, %1, %2, %3;" : "=l"(d) : "l"(a), "l"(b), "l"(c));
    return d;
}
__device__ __forceinline__ unsigned long long dup2(float x) {
    unsigned long long r;
    asm("mov.b64 %0, {%1, %1};" : "=l"(r) : "f"(x));
    return r;
}
__device__ __forceinline__ float2 unpk(unsigned long long v) {
    float2 f;
    asm("mov.b64 {%0, %1}, %2;" : "=f"(f.x), "=f"(f.y) : "l"(v));
    return f;
}
// feature map: elu(x)+1 = x>0 ? x+1 : exp(x)
__device__ __forceinline__ float fm(float x) {
    return x > 0.0f ? x + 1.0f : __expf(x);
}

// ---------------- phase 1: kv partials + ksum partials ----------------
__global__ __launch_bounds__(256) void phase1_kernel(const float* __restrict__ k,
                                                     const float* __restrict__ v) {
    __shared__ float kf_s[16 * 64];
    __shared__ float v_s[16 * 64];
    __shared__ float ksum_sm[64];

    const int t = threadIdx.x;
    const int sx = blockIdx.x;   // split
    const int b  = blockIdx.y;   // batch
    const int row = t >> 4;          // 0..15 (load row within chunk)
    const int c4  = (t & 15) * 4;    // 0,4,...,60 (load col)
    const int ty = t >> 4;           // d-tile 0..15
    const int tx = t & 15;           // e-tile 0..15

    const float* kp = k + ((size_t)b * SS + (size_t)sx * ROWS_P1) * DDIM;
    const float* vp = v + ((size_t)b * SS + (size_t)sx * ROWS_P1) * DDIM;

    if (t < 64) ksum_sm[t] = 0.0f;

    unsigned long long acc[4][2];
#pragma unroll
    for (int i = 0; i < 4; i++) { acc[i][0] = 0ull; acc[i][1] = 0ull; }
    float ks0 = 0.f, ks1 = 0.f, ks2 = 0.f, ks3 = 0.f;

    for (int ch = 0; ch < ROWS_P1 / 16; ch++) {
        float4 k4 = *(const float4*)(kp + (size_t)(ch * 16 + row) * DDIM + c4);
        float4 v4 = *(const float4*)(vp + (size_t)(ch * 16 + row) * DDIM + c4);
        k4.x = fm(k4.x); k4.y = fm(k4.y); k4.z = fm(k4.z); k4.w = fm(k4.w);
        ks0 += k4.x; ks1 += k4.y; ks2 += k4.z; ks3 += k4.w;

        __syncthreads();   // previous chunk fully consumed
        *(float4*)&kf_s[row * 64 + c4] = k4;
        *(float4*)&v_s[row * 64 + c4]  = v4;
        __syncthreads();

#pragma unroll
        for (int ss2 = 0; ss2 < 16; ss2++) {
            float4 a4 = *(const float4*)&kf_s[ss2 * 64 + ty * 4];
            const unsigned long long* vu =
                (const unsigned long long*)&v_s[ss2 * 64 + tx * 4];
            unsigned long long b0 = vu[0];
            unsigned long long b1 = vu[1];
            unsigned long long a;
            a = dup2(a4.x); acc[0][0] = ffma2(a, b0, acc[0][0]); acc[0][1] = ffma2(a, b1, acc[0][1]);
            a = dup2(a4.y); acc[1][0] = ffma2(a, b0, acc[1][0]); acc[1][1] = ffma2(a, b1, acc[1][1]);
            a = dup2(a4.z); acc[2][0] = ffma2(a, b0, acc[2][0]); acc[2][1] = ffma2(a, b1, acc[2][1]);
            a = dup2(a4.w); acc[3][0] = ffma2(a, b0, acc[3][0]); acc[3][1] = ffma2(a, b1, acc[3][1]);
        }
    }

    // ksum block reduction (thread loaded columns c4..c4+3 across all its rows)
    atomicAdd(&ksum_sm[c4 + 0], ks0);
    atomicAdd(&ksum_sm[c4 + 1], ks1);
    atomicAdd(&ksum_sm[c4 + 2], ks2);
    atomicAdd(&ksum_sm[c4 + 3], ks3);
    __syncthreads();

    float* outp = g_part + ((size_t)sx * BB + b) * (DDIM * DDIM);
#pragma unroll
    for (int i = 0; i < 4; i++) {
        float2 lo = unpk(acc[i][0]);
        float2 hi = unpk(acc[i][1]);
        float4 o4 = make_float4(lo.x, lo.y, hi.x, hi.y);
        *(float4*)(outp + (size_t)(ty * 4 + i) * DDIM + tx * 4) = o4;
    }
    if (t < 64) g_ksum_part[((size_t)sx * BB + b) * DDIM + t] = ksum_sm[t];
}

// ---------------- combine: sum SPLIT partials ----------------
__global__ __launch_bounds__(256) void combine_kernel() {
    const int idx = blockIdx.x * 256 + threadIdx.x;
    const int n1 = BB * DDIM * DDIM;   // 262144
    if (idx < n1) {
        float s = 0.0f;
#pragma unroll
        for (int p = 0; p < SPLIT; p++)
            s += g_part[(size_t)p * n1 + idx];
        g_kv[idx] = s;
    } else if (idx - n1 < BB * DDIM) {
        const int j = idx - n1;
        float s = 0.0f;
#pragma unroll
        for (int p = 0; p < SPLIT; p++)
            s += g_ksum_part[(size_t)p * (BB * DDIM) + j];
        g_ksum[j] = s;
    }
}

// ---------------- phase 2: o = (qf @ kv) / max(qf.ksum, 1e-4) ----------------
#define QF_STRIDE 68   // padded row stride (floats), 16B-aligned rows, breaks bank conflicts

__global__ __launch_bounds__(256) void phase2_kernel(const float* __restrict__ q,
                                                     float* __restrict__ o) {
    __shared__ float kv_s[64 * 64];          // 16 KB
    __shared__ float qf_s[64 * QF_STRIDE];   // 17 KB
    __shared__ float ksum_s[64];
    __shared__ float invden_s[64];

    const int t  = threadIdx.x;
    const int b  = blockIdx.y;
    const int s0 = blockIdx.x * 64;

    // load kv (16KB) + ksum
    const float* kvsrc = g_kv + (size_t)b * (DDIM * DDIM);
#pragma unroll
    for (int kk = 0; kk < 4; kk++) {
        int f = t + kk * 256;   // float4 index 0..1023
        *(float4*)&kv_s[f * 4] = *(const float4*)(kvsrc + (size_t)f * 4);
    }
    if (t < 64) ksum_s[t] = g_ksum[(size_t)b * DDIM + t];
    __syncthreads();

    // q load -> qf smem (+ per-row denominator via quad reduction)
    {
        const int row = t >> 2;            // 0..63
        const int qd  = (t & 3) * 16;      // d-chunk base
        const float* qp = q + ((size_t)b * SS + s0 + row) * DDIM + qd;
        float pden = 0.0f;
#pragma unroll
        for (int j = 0; j < 4; j++) {
            float4 q4 = *(const float4*)(qp + 4 * j);
            q4.x = fm(q4.x); q4.y = fm(q4.y); q4.z = fm(q4.z); q4.w = fm(q4.w);
            float4 ks = *(const float4*)&ksum_s[qd + 4 * j];
            pden += q4.x * ks.x + q4.y * ks.y + q4.z * ks.z + q4.w * ks.w;
            *(float4*)&qf_s[row * QF_STRIDE + qd + 4 * j] = q4;
        }
        pden += __shfl_xor_sync(0xffffffffu, pden, 1);
        pden += __shfl_xor_sync(0xffffffffu, pden, 2);
        if ((t & 3) == 0) invden_s[row] = 1.0f / fmaxf(pden, 1e-4f);
    }
    __syncthreads();

    const int ty = t >> 4;   // s-tile 0..15
    const int tx = t & 15;   // e-tile 0..15
    unsigned long long acc[4][2];
#pragma unroll
    for (int i = 0; i < 4; i++) { acc[i][0] = 0ull; acc[i][1] = 0ull; }

    const unsigned long long* kv_u = (const unsigned long long*)kv_s;

#define P2_STEP(DD_, COMP_)                                                        \
    {                                                                              \
        unsigned long long b0 = kv_u[(size_t)(dg + DD_) * 32 + tx * 2];            \
        unsigned long long b1 = kv_u[(size_t)(dg + DD_) * 32 + tx * 2 + 1];        \
        unsigned long long a;                                                      \
        a = dup2(qa0.COMP_); acc[0][0] = ffma2(a, b0, acc[0][0]); acc[0][1] = ffma2(a, b1, acc[0][1]); \
        a = dup2(qa1.COMP_); acc[1][0] = ffma2(a, b0, acc[1][0]); acc[1][1] = ffma2(a, b1, acc[1][1]); \
        a = dup2(qa2.COMP_); acc[2][0] = ffma2(a, b0, acc[2][0]); acc[2][1] = ffma2(a, b1, acc[2][1]); \
        a = dup2(qa3.COMP_); acc[3][0] = ffma2(a, b0, acc[3][0]); acc[3][1] = ffma2(a, b1, acc[3][1]); \
    }

#pragma unroll
    for (int dg = 0; dg < 64; dg += 4) {
        float4 qa0 = *(const float4*)&qf_s[(ty * 4 + 0) * QF_STRIDE + dg];
        float4 qa1 = *(const float4*)&qf_s[(ty * 4 + 1) * QF_STRIDE + dg];
        float4 qa2 = *(const float4*)&qf_s[(ty * 4 + 2) * QF_STRIDE + dg];
        float4 qa3 = *(const float4*)&qf_s[(ty * 4 + 3) * QF_STRIDE + dg];
        P2_STEP(0, x)
        P2_STEP(1, y)
        P2_STEP(2, z)
        P2_STEP(3, w)
    }
#undef P2_STEP

    float* op = o + ((size_t)b * SS + s0) * DDIM;
#pragma unroll
    for (int i = 0; i < 4; i++) {
        int sr = ty * 4 + i;
        float inv = invden_s[sr];
        float2 lo = unpk(acc[i][0]);
        float2 hi = unpk(acc[i][1]);
        float4 o4 = make_float4(lo.x * inv, lo.y * inv, hi.x * inv, hi.y * inv);
        *(float4*)(op + (size_t)sr * DDIM + tx * 4) = o4;
    }
}

// ---------------- launch ----------------
extern "C" void kernel_launch(void* const* d_in, const int* in_sizes, int n_in,
                              void* d_out, int out_size) {
    (void)in_sizes; (void)n_in; (void)out_size;
    const float* q = (const float*)d_in[0];
    const float* k = (const float*)d_in[1];
    const float* v = (const float*)d_in[2];
    float* o = (float*)d_out;

    dim3 g1(SPLIT, BB);
    phase1_kernel<<<g1, 256>>>(k, v);

    const int ntot = BB * DDIM * DDIM + BB * DDIM;
    combine_kernel<<<(ntot + 255) / 256, 256>>>();

    dim3 g2(SS / 64, BB);
    phase2_kernel<<<g2, 256>>>(q, o);
}

// round 3
// speedup vs baseline: 1.6809x; 1.6809x over previous
#include <cuda_runtime.h>

#define BB 64
#define SS 8192
#define DDIM 64
#define SPLIT 16
#define ROWS_P1 (SS / SPLIT)   // 512
#define CH 32
#define NCHUNK (ROWS_P1 / CH)  // 16

__device__ float g_part[SPLIT * BB * DDIM * DDIM];
__device__ float g_ksum_part[SPLIT * BB * DDIM];
__device__ float g_kv[BB * DDIM * DDIM];
__device__ float g_ksum[BB * DDIM];

__device__ __forceinline__ unsigned long long ffma2(unsigned long long a,
                                                    unsigned long long b,
                                                    unsigned long long c) {
    unsigned long long d;
    asm("fma.rn.f32x2 %0, %1, %2, %3;" : "=l"(d) : "l"(a), "l"(b), "l"(c));
    return d;
}
__device__ __forceinline__ unsigned long long dup2(float x) {
    unsigned long long r;
    asm("mov.b64 %0, {%1, %1};" : "=l"(r) : "f"(x));
    return r;
}
__device__ __forceinline__ float2 unpk(unsigned long long v) {
    float2 f;
    asm("mov.b64 {%0, %1}, %2;" : "=f"(f.x), "=f"(f.y) : "l"(v));
    return f;
}
__device__ __forceinline__ float fm(float x) {   // elu(x)+1
    return x > 0.0f ? x + 1.0f : __expf(x);
}
__device__ __forceinline__ unsigned su32(const void* p) {
    unsigned r;
    asm("{ .reg .u64 t; cvta.to.shared.u64 t, %1; cvt.u32.u64 %0, t; }" : "=r"(r) : "l"(p));
    return r;
}
__device__ __forceinline__ void cp16(unsigned s, const void* g) {
    asm volatile("cp.async.cg.shared.global [%0], [%1], 16;" :: "r"(s), "l"(g));
}
#define CP_COMMIT() asm volatile("cp.async.commit_group;")
#define CP_WAIT(N)  asm volatile("cp.async.wait_group %0;" :: "n"(N))

// ---------------- phase 1 ----------------
__global__ __launch_bounds__(256) void phase1_kernel(const float* __restrict__ k,
                                                     const float* __restrict__ v) {
    __shared__ float kf_s[2][CH * 64];
    __shared__ float v_s[2][CH * 64];
    __shared__ float ksum_sm[64];

    const int t = threadIdx.x;
    const int sx = blockIdx.x, b = blockIdx.y;
    const int ty = t >> 4, tx = t & 15;
    const int lc4 = (t & 15) * 4;

    const float* kp = k + ((size_t)b * SS + (size_t)sx * ROWS_P1) * DDIM;
    const float* vp = v + ((size_t)b * SS + (size_t)sx * ROWS_P1) * DDIM;
    if (t < 64) ksum_sm[t] = 0.0f;

    const unsigned ksm[2] = { su32(&kf_s[0][0]), su32(&kf_s[1][0]) };
    const unsigned vsm[2] = { su32(&v_s[0][0]),  su32(&v_s[1][0]) };

    // prologue: chunk 0 -> buf 0
#pragma unroll
    for (int i = 0; i < 2; i++) {
        int g = t + i * 256;
        size_t off = (size_t)(g >> 4) * DDIM + (g & 15) * 4;
        cp16(ksm[0] + g * 16, kp + off);
        cp16(vsm[0] + g * 16, vp + off);
    }
    CP_COMMIT();

    unsigned long long acc[4][2];
#pragma unroll
    for (int i = 0; i < 4; i++) { acc[i][0] = 0ull; acc[i][1] = 0ull; }
    float p0 = 0.f, p1 = 0.f, p2 = 0.f, p3 = 0.f;

    for (int ch = 0; ch < NCHUNK; ch++) {
        const int buf = ch & 1;
        CP_WAIT(0);
        __syncthreads();
        // fm in place + ksum partials
        {
            float4* kb = (float4*)&kf_s[buf][0];
#pragma unroll
            for (int i = 0; i < 2; i++) {
                float4 x = kb[t + i * 256];
                x.x = fm(x.x); x.y = fm(x.y); x.z = fm(x.z); x.w = fm(x.w);
                p0 += x.x; p1 += x.y; p2 += x.z; p3 += x.w;
                kb[t + i * 256] = x;
            }
        }
        __syncthreads();
        if (ch + 1 < NCHUNK) {   // prefetch next chunk (other buffer is free now)
#pragma unroll
            for (int i = 0; i < 2; i++) {
                int g = t + i * 256;
                size_t off = (size_t)((ch + 1) * CH + (g >> 4)) * DDIM + (g & 15) * 4;
                cp16(ksm[buf ^ 1] + g * 16, kp + off);
                cp16(vsm[buf ^ 1] + g * 16, vp + off);
            }
            CP_COMMIT();
        }
#pragma unroll
        for (int s2 = 0; s2 < CH; s2++) {
            float4 a4 = *(const float4*)&kf_s[buf][s2 * 64 + ty * 4];
            const unsigned long long* vu = (const unsigned long long*)&v_s[buf][s2 * 64 + tx * 4];
            unsigned long long b0 = vu[0], b1 = vu[1], a;
            a = dup2(a4.x); acc[0][0] = ffma2(a, b0, acc[0][0]); acc[0][1] = ffma2(a, b1, acc[0][1]);
            a = dup2(a4.y); acc[1][0] = ffma2(a, b0, acc[1][0]); acc[1][1] = ffma2(a, b1, acc[1][1]);
            a = dup2(a4.z); acc[2][0] = ffma2(a, b0, acc[2][0]); acc[2][1] = ffma2(a, b1, acc[2][1]);
            a = dup2(a4.w); acc[3][0] = ffma2(a, b0, acc[3][0]); acc[3][1] = ffma2(a, b1, acc[3][1]);
        }
    }

    atomicAdd(&ksum_sm[lc4 + 0], p0);
    atomicAdd(&ksum_sm[lc4 + 1], p1);
    atomicAdd(&ksum_sm[lc4 + 2], p2);
    atomicAdd(&ksum_sm[lc4 + 3], p3);
    __syncthreads();

    float* outp = g_part + ((size_t)sx * BB + b) * (DDIM * DDIM);
#pragma unroll
    for (int i = 0; i < 4; i++) {
        float2 lo = unpk(acc[i][0]);
        float2 hi = unpk(acc[i][1]);
        *(float4*)(outp + (size_t)(ty * 4 + i) * DDIM + tx * 4) =
            make_float4(lo.x, lo.y, hi.x, hi.y);
    }
    if (t < 64) g_ksum_part[((size_t)sx * BB + b) * DDIM + t] = ksum_sm[t];
}

// ---------------- combine ----------------
__global__ __launch_bounds__(256) void combine_kernel() {
    const int idx = blockIdx.x * 256 + threadIdx.x;
    const int n1 = BB * DDIM * DDIM;
    if (idx < n1) {
        float s = 0.0f;
#pragma unroll
        for (int p = 0; p < SPLIT; p++) s += g_part[(size_t)p * n1 + idx];
        g_kv[idx] = s;
    } else if (idx - n1 < BB * DDIM) {
        const int j = idx - n1;
        float s = 0.0f;
#pragma unroll
        for (int p = 0; p < SPLIT; p++) s += g_ksum_part[(size_t)p * (BB * DDIM) + j];
        g_ksum[j] = s;
    }
}

// ---------------- phase 2: 128 rows/block, cp.async pipelined ----------------
#define P2_SMEM (16384 + 32768 + 512)

__global__ __launch_bounds__(256) void phase2_kernel(const float* __restrict__ q,
                                                     float* __restrict__ o) {
    extern __shared__ char sm[];
    float* kv_s     = (float*)sm;                  // 64x64
    float* qb       = (float*)(sm + 16384);        // 2 x 64x64
    float* ksum_s   = (float*)(sm + 49152);
    float* invden_s = (float*)(sm + 49408);

    const int t = threadIdx.x;
    const int b = blockIdx.y;
    const int s0 = blockIdx.x * 128;
    const unsigned skv = su32(kv_s), sqb = su32(qb);

    const float* kvsrc = g_kv + (size_t)b * 4096;
    const float* qp = q + ((size_t)b * SS + s0) * DDIM;
#pragma unroll
    for (int i = 0; i < 4; i++) cp16(skv + (t + i * 256) * 16, kvsrc + (size_t)(t + i * 256) * 4);
#pragma unroll
    for (int i = 0; i < 4; i++) cp16(sqb + (t + i * 256) * 16, qp + (size_t)(t + i * 256) * 4);
    CP_COMMIT();
#pragma unroll
    for (int i = 0; i < 4; i++) cp16(sqb + 16384 + (t + i * 256) * 16, qp + 4096 + (size_t)(t + i * 256) * 4);
    CP_COMMIT();
    if (t < 64) ksum_s[t] = g_ksum[(size_t)b * DDIM + t];
    CP_WAIT(1);
    __syncthreads();

    const int ty = t >> 4, tx = t & 15;
    const unsigned long long* kv_u = (const unsigned long long*)kv_s;

#pragma unroll 1
    for (int half = 0; half < 2; half++) {
        if (half == 1) { CP_WAIT(0); __syncthreads(); }
        float* qf = qb + half * 4096;
        // fm + denominator
        {
            const int row = t >> 2;
            const int qd = (t & 3) * 16;
            float pden = 0.0f;
#pragma unroll
            for (int j = 0; j < 4; j++) {
                float4 q4 = *(float4*)(qf + row * 64 + qd + 4 * j);
                q4.x = fm(q4.x); q4.y = fm(q4.y); q4.z = fm(q4.z); q4.w = fm(q4.w);
                float4 ks = *(const float4*)&ksum_s[qd + 4 * j];
                pden += q4.x * ks.x + q4.y * ks.y + q4.z * ks.z + q4.w * ks.w;
                *(float4*)(qf + row * 64 + qd + 4 * j) = q4;
            }
            pden += __shfl_xor_sync(0xffffffffu, pden, 1);
            pden += __shfl_xor_sync(0xffffffffu, pden, 2);
            if ((t & 3) == 0) invden_s[row] = 1.0f / fmaxf(pden, 1e-4f);
        }
        __syncthreads();

        unsigned long long acc[4][2];
#pragma unroll
        for (int i = 0; i < 4; i++) { acc[i][0] = 0ull; acc[i][1] = 0ull; }

#define P2_STEP(DD_, COMP_)                                                        \
        {                                                                          \
            unsigned long long b0 = kv_u[(size_t)(dg + DD_) * 32 + tx * 2];        \
            unsigned long long b1 = kv_u[(size_t)(dg + DD_) * 32 + tx * 2 + 1];    \
            unsigned long long a;                                                  \
            a = dup2(qa0.COMP_); acc[0][0] = ffma2(a, b0, acc[0][0]); acc[0][1] = ffma2(a, b1, acc[0][1]); \
            a = dup2(qa1.COMP_); acc[1][0] = ffma2(a, b0, acc[1][0]); acc[1][1] = ffma2(a, b1, acc[1][1]); \
            a = dup2(qa2.COMP_); acc[2][0] = ffma2(a, b0, acc[2][0]); acc[2][1] = ffma2(a, b1, acc[2][1]); \
            a = dup2(qa3.COMP_); acc[3][0] = ffma2(a, b0, acc[3][0]); acc[3][1] = ffma2(a, b1, acc[3][1]); \
        }
#pragma unroll
        for (int dg = 0; dg < 64; dg += 4) {
            float4 qa0 = *(const float4*)(qf + (ty * 4 + 0) * 64 + dg);
            float4 qa1 = *(const float4*)(qf + (ty * 4 + 1) * 64 + dg);
            float4 qa2 = *(const float4*)(qf + (ty * 4 + 2) * 64 + dg);
            float4 qa3 = *(const float4*)(qf + (ty * 4 + 3) * 64 + dg);
            P2_STEP(0, x) P2_STEP(1, y) P2_STEP(2, z) P2_STEP(3, w)
        }
#undef P2_STEP

        float* op = o + ((size_t)b * SS + s0 + half * 64) * DDIM;
#pragma unroll
        for (int i = 0; i < 4; i++) {
            int sr = ty * 4 + i;
            float inv = invden_s[sr];
            float2 lo = unpk(acc[i][0]);
            float2 hi = unpk(acc[i][1]);
            *(float4*)(op + (size_t)sr * DDIM + tx * 4) =
                make_float4(lo.x * inv, lo.y * inv, hi.x * inv, hi.y * inv);
        }
    }
}

// ---------------- launch ----------------
extern "C" void kernel_launch(void* const* d_in, const int* in_sizes, int n_in,
                              void* d_out, int out_size) {
    (void)in_sizes; (void)n_in; (void)out_size;
    const float* q = (const float*)d_in[0];
    const float* k = (const float*)d_in[1];
    const float* v = (const float*)d_in[2];
    float* o = (float*)d_out;

    cudaFuncSetAttribute(phase2_kernel, cudaFuncAttributeMaxDynamicSharedMemorySize, P2_SMEM);

    dim3 g1(SPLIT, BB);
    phase1_kernel<<<g1, 256>>>(k, v);

    const int ntot = BB * DDIM * DDIM + BB * DDIM;
    combine_kernel<<<(ntot + 255) / 256, 256>>>();

    dim3 g2(SS / 128, BB);
    phase2_kernel<<<g2, 256, P2_SMEM>>>(q, o);
}

// round 5
// speedup vs baseline: 2.2548x; 1.3414x over previous
#include <cuda_runtime.h>
#include <cuda_bf16.h>
#include <cstdint>

#define BB 64
#define SS 8192
#define DDIM 64
#define SPLIT 16
#define ROWS_P1 (SS / SPLIT)   // 512
#define CH 32
#define NCHUNK (ROWS_P1 / CH)  // 16
#define TP 17                  // phase1 tile pad (words/row)

__device__ float    g_part[SPLIT * BB * DDIM * DDIM];
__device__ float    g_ksum_part[SPLIT * BB * DDIM];
__device__ uint32_t g_bhi[BB * DDIM * 32];   // kvT bf16-hi packed words [b][e][32]
__device__ uint32_t g_blo[BB * DDIM * 32];
__device__ float    g_ksum[BB * DDIM];

// ---------------- helpers ----------------
__device__ __forceinline__ float fm(float x) { return x > 0.0f ? x + 1.0f : __expf(x); }
__device__ __forceinline__ unsigned su32(const void* p) {
    unsigned r;
    asm("{ .reg .u64 t; cvta.to.shared.u64 t, %1; cvt.u32.u64 %0, t; }" : "=r"(r) : "l"(p));
    return r;
}
__device__ __forceinline__ void cp16(unsigned s, const void* g) {
    asm volatile("cp.async.cg.shared.global [%0], [%1], 16;" :: "r"(s), "l"(g));
}
#define CP_COMMIT() asm volatile("cp.async.commit_group;")
#define CP_WAIT(N)  asm volatile("cp.async.wait_group %0;" :: "n"(N))

__device__ __forceinline__ uint32_t pklh(float lo, float hi) {  // lo -> low 16
    uint32_t r;
    asm("cvt.rn.bf16x2.f32 %0, %1, %2;" : "=r"(r) : "f"(hi), "f"(lo));
    return r;
}
__device__ __forceinline__ uint32_t prmt7632(uint32_t a, uint32_t b) {
    uint32_t r; asm("prmt.b32 %0, %1, %2, 0x7632;" : "=r"(r) : "r"(a), "r"(b)); return r;
}
// truncation split of 2 fp32 -> packed bf16 hi word + bf16 lo word
__device__ __forceinline__ void split2(float x0, float x1, uint32_t& hw, uint32_t& lw) {
    uint32_t u0 = __float_as_uint(x0), u1 = __float_as_uint(x1);
    hw = prmt7632(u0, u1);
    float l0 = x0 - __uint_as_float(u0 & 0xFFFF0000u);
    float l1 = x1 - __uint_as_float(u1 & 0xFFFF0000u);
    lw = pklh(l0, l1);
}
__device__ __forceinline__ void mma_bf16(float* c, const uint32_t* a, uint32_t b0, uint32_t b1) {
    asm volatile("mma.sync.aligned.m16n8k16.row.col.f32.bf16.bf16.f32 "
                 "{%0,%1,%2,%3},{%4,%5,%6,%7},{%8,%9},{%0,%1,%2,%3};"
                 : "+f"(c[0]), "+f"(c[1]), "+f"(c[2]), "+f"(c[3])
                 : "r"(a[0]), "r"(a[1]), "r"(a[2]), "r"(a[3]), "r"(b0), "r"(b1));
}

// ---------------- phase 1: kvT partials via HMMA ----------------
// D[e][d] = sum_s v[s][e] * kf[s][d];  A = vT (m=e,k=s), B = kf (k=s,n=d)
#define P1_STG   0        // 2 bufs x (k,v) x 2048 f32 = 32768 B
#define P1_KFH   32768    // [64][TP] words = 4352 B
#define P1_KFL   37120
#define P1_VTH   41472
#define P1_VTL   45824
#define P1_KSUM  50176
#define P1_SMEM  50432

__global__ __launch_bounds__(256) void phase1_kernel(const float* __restrict__ k,
                                                     const float* __restrict__ v) {
    extern __shared__ char smx[];
    uint32_t* kfTh = (uint32_t*)(smx + P1_KFH);
    uint32_t* kfTl = (uint32_t*)(smx + P1_KFL);
    uint32_t* vTh  = (uint32_t*)(smx + P1_VTH);
    uint32_t* vTl  = (uint32_t*)(smx + P1_VTL);
    float* ksum_sm = (float*)(smx + P1_KSUM);

    const int t = threadIdx.x, w = t >> 5, lane = t & 31;
    const int g = lane >> 2, tig = lane & 3;
    const int sx = blockIdx.x, b = blockIdx.y;
    const float* kp = k + ((size_t)b * SS + (size_t)sx * ROWS_P1) * DDIM;
    const float* vp = v + ((size_t)b * SS + (size_t)sx * ROWS_P1) * DDIM;
    const unsigned sstg = su32(smx);

    if (t < 64) ksum_sm[t] = 0.0f;

    // prefetch chunk 0 -> buf0, chunk 1 -> buf1
#pragma unroll
    for (int c = 0; c < 2; c++) {
        const float* kb = kp + (size_t)c * 2048;
        const float* vb = vp + (size_t)c * 2048;
        unsigned d0 = sstg + c * 16384;
        cp16(d0 + t * 16, kb + t * 4);
        cp16(d0 + (t + 256) * 16, kb + (t + 256) * 4);
        cp16(d0 + 8192 + t * 16, vb + t * 4);
        cp16(d0 + 8192 + (t + 256) * 16, vb + (t + 256) * 4);
        CP_COMMIT();
    }

    const int eb = (w & 3) * 16;        // warp m-tile (e rows)
    const int nb = (w >> 2) * 4;        // warp n-tile group (4 tiles of 8 d)
    float acc[4][4];
#pragma unroll
    for (int i = 0; i < 4; i++)
#pragma unroll
        for (int j = 0; j < 4; j++) acc[i][j] = 0.0f;
    float ksl = 0.0f;

    const int td = t & 63, sgb = (t >> 6) * 8;   // transpose-pass mapping

    for (int ch = 0; ch < NCHUNK; ch++) {
        const int buf = ch & 1;
        if (ch < NCHUNK - 1) CP_WAIT(1); else CP_WAIT(0);
        __syncthreads();   // staging ready + previous mma done

        // transpose/convert: k -> fm -> split -> kfT ; v -> split -> vT
        {
            const float* sk = (const float*)(smx + buf * 16384);
            const float* sv = sk + 2048;
            float x[8];
#pragma unroll
            for (int i = 0; i < 8; i++) {
                float y = fm(sk[(sgb + i) * 64 + td]);
                ksl += y; x[i] = y;
            }
#pragma unroll
            for (int j = 0; j < 4; j++) {
                uint32_t hw, lw;
                split2(x[2 * j], x[2 * j + 1], hw, lw);
                kfTh[td * TP + sgb / 2 + j] = hw;
                kfTl[td * TP + sgb / 2 + j] = lw;
            }
#pragma unroll
            for (int i = 0; i < 8; i++) x[i] = sv[(sgb + i) * 64 + td];
#pragma unroll
            for (int j = 0; j < 4; j++) {
                uint32_t hw, lw;
                split2(x[2 * j], x[2 * j + 1], hw, lw);
                vTh[td * TP + sgb / 2 + j] = hw;
                vTl[td * TP + sgb / 2 + j] = lw;
            }
        }
        __syncthreads();   // tiles ready, staging[buf] free

        if (ch + 2 < NCHUNK) {
            const float* kb = kp + (size_t)(ch + 2) * 2048;
            const float* vb = vp + (size_t)(ch + 2) * 2048;
            unsigned d0 = sstg + buf * 16384;
            cp16(d0 + t * 16, kb + t * 4);
            cp16(d0 + (t + 256) * 16, kb + (t + 256) * 4);
            cp16(d0 + 8192 + t * 16, vb + t * 4);
            cp16(d0 + 8192 + (t + 256) * 16, vb + (t + 256) * 4);
            CP_COMMIT();
        }

#pragma unroll
        for (int ks = 0; ks < 2; ks++) {
            const int sp = ks * 8 + tig;
            const int e0 = eb + g;
            uint32_t ah[4], al[4];
            ah[0] = vTh[e0 * TP + sp];       ah[1] = vTh[(e0 + 8) * TP + sp];
            ah[2] = vTh[e0 * TP + sp + 4];   ah[3] = vTh[(e0 + 8) * TP + sp + 4];
            al[0] = vTl[e0 * TP + sp];       al[1] = vTl[(e0 + 8) * TP + sp];
            al[2] = vTl[e0 * TP + sp + 4];   al[3] = vTl[(e0 + 8) * TP + sp + 4];
#pragma unroll
            for (int nt = 0; nt < 4; nt++) {
                const int d0 = (nb + nt) * 8 + g;
                uint32_t bh0 = kfTh[d0 * TP + sp], bh1 = kfTh[d0 * TP + sp + 4];
                uint32_t bl0 = kfTl[d0 * TP + sp], bl1 = kfTl[d0 * TP + sp + 4];
                mma_bf16(acc[nt], ah, bh0, bh1);
                mma_bf16(acc[nt], ah, bl0, bl1);
                mma_bf16(acc[nt], al, bh0, bh1);
            }
        }
    }

    // epilogue: partials to g_part (orientation [e][d]) + ksum
    {
        float* op = g_part + ((size_t)sx * BB + b) * 4096;
#pragma unroll
        for (int nt = 0; nt < 4; nt++) {
            const int e0 = eb + g, d0 = (nb + nt) * 8 + tig * 2;
            *(float2*)(op + (size_t)e0 * 64 + d0)       = make_float2(acc[nt][0], acc[nt][1]);
            *(float2*)(op + (size_t)(e0 + 8) * 64 + d0) = make_float2(acc[nt][2], acc[nt][3]);
        }
    }
    atomicAdd(&ksum_sm[td], ksl);
    __syncthreads();
    if (t < 64) g_ksum_part[((size_t)sx * BB + b) * 64 + t] = ksum_sm[t];
}

// ---------------- combine: sum partials -> bf16 hi/lo word arrays ----------------
__global__ __launch_bounds__(256) void combine_kernel() {
    const int b = blockIdx.x, t = threadIdx.x;
    if (t < 64) {
        float s = 0.0f;
#pragma unroll
        for (int p = 0; p < SPLIT; p++) s += g_ksum_part[((size_t)p * BB + b) * 64 + t];
        g_ksum[(size_t)b * 64 + t] = s;
    }
#pragma unroll
    for (int i = 0; i < 8; i++) {
        const int p = t + i * 256;             // pair index = e*32 + word
        const int e = p >> 5, d0 = (p & 31) * 2;
        float s0 = 0.0f, s1 = 0.0f;
#pragma unroll
        for (int sp = 0; sp < SPLIT; sp++) {
            float2 x = *(const float2*)(g_part + ((size_t)sp * BB + b) * 4096 + (size_t)e * 64 + d0);
            s0 += x.x; s1 += x.y;
        }
        uint32_t hw, lw;
        split2(s0, s1, hw, lw);
        g_bhi[(size_t)b * 2048 + p] = hw;
        g_blo[(size_t)b * 2048 + p] = lw;
    }
}

// ---------------- phase 2: o = (qf @ kv) / deno via HMMA ----------------
// D[s][e] = qf[s][d] * kv[d][e];  A = qf (m=s,k=d), B = kvT words (k=d,n=e)
#define P2_AH   0          // [128][33] words = 16896 B
#define P2_AL   16896
#define P2_BH   33792      // [64][36] words = 9216 B
#define P2_BL   43008
#define P2_KS   52224
#define P2_ID   52480
#define P2_SMEM 52992

__global__ __launch_bounds__(256) void phase2_kernel(const float* __restrict__ q,
                                                     float* __restrict__ o) {
    extern __shared__ char smx[];
    uint32_t* Ah = (uint32_t*)(smx + P2_AH);
    uint32_t* Al = (uint32_t*)(smx + P2_AL);
    uint32_t* Bh = (uint32_t*)(smx + P2_BH);
    uint32_t* Bl = (uint32_t*)(smx + P2_BL);
    float* ksum_s = (float*)(smx + P2_KS);
    float* iden   = (float*)(smx + P2_ID);

    const int t = threadIdx.x, w = t >> 5, lane = t & 31;
    const int g = lane >> 2, tig = lane & 3;
    const int b = blockIdx.y, s0 = blockIdx.x * 128;

    if (t < 64) ksum_s[t] = g_ksum[(size_t)b * 64 + t];
    // B copy (512 uint4 per matrix)
    {
        const uint4* gh = (const uint4*)(g_bhi + (size_t)b * 2048);
        const uint4* gl = (const uint4*)(g_blo + (size_t)b * 2048);
#pragma unroll
        for (int i = 0; i < 2; i++) {
            int idx = t + i * 256;
            int e = idx >> 3, w4 = (idx & 7) * 4;
            *(uint4*)&Bh[e * 36 + w4] = gh[idx];
            *(uint4*)&Bl[e * 36 + w4] = gl[idx];
        }
    }
    __syncthreads();   // ksum ready

    // A conversion + denominator
    {
        const int s = t >> 1, dh = (t & 1) * 32;
        const float* qp = q + ((size_t)b * SS + s0 + s) * 64 + dh;
        float pden = 0.0f;
#pragma unroll
        for (int j = 0; j < 4; j++) {
            float4 x = *(const float4*)(qp + j * 8);
            float4 y = *(const float4*)(qp + j * 8 + 4);
            x.x = fm(x.x); x.y = fm(x.y); x.z = fm(x.z); x.w = fm(x.w);
            y.x = fm(y.x); y.y = fm(y.y); y.z = fm(y.z); y.w = fm(y.w);
            const float* ks = &ksum_s[dh + j * 8];
            pden += x.x * ks[0] + x.y * ks[1] + x.z * ks[2] + x.w * ks[3]
                  + y.x * ks[4] + y.y * ks[5] + y.z * ks[6] + y.w * ks[7];
            uint32_t hw, lw;
            const int wb = s * 33 + (t & 1) * 16 + j * 4;
            split2(x.x, x.y, hw, lw); Ah[wb + 0] = hw; Al[wb + 0] = lw;
            split2(x.z, x.w, hw, lw); Ah[wb + 1] = hw; Al[wb + 1] = lw;
            split2(y.x, y.y, hw, lw); Ah[wb + 2] = hw; Al[wb + 2] = lw;
            split2(y.z, y.w, hw, lw); Ah[wb + 3] = hw; Al[wb + 3] = lw;
        }
        pden += __shfl_xor_sync(0xffffffffu, pden, 1);
        if (!(t & 1)) iden[s] = 1.0f / fmaxf(pden, 1e-4f);
    }
    __syncthreads();

    const int sbw = (w & 3) * 32;       // warp covers 2 m-tiles (32 s-rows)
    const int nb = (w >> 2) * 4;        // 4 n-tiles
    float acc[2][4][4];
#pragma unroll
    for (int m = 0; m < 2; m++)
#pragma unroll
        for (int i = 0; i < 4; i++)
#pragma unroll
            for (int j = 0; j < 4; j++) acc[m][i][j] = 0.0f;

#pragma unroll
    for (int ks = 0; ks < 4; ks++) {
        const int sp = ks * 8 + tig;
        uint32_t ah[2][4], al[2][4];
#pragma unroll
        for (int m = 0; m < 2; m++) {
            const int r = sbw + m * 16 + g;
            ah[m][0] = Ah[r * 33 + sp];       ah[m][1] = Ah[(r + 8) * 33 + sp];
            ah[m][2] = Ah[r * 33 + sp + 4];   ah[m][3] = Ah[(r + 8) * 33 + sp + 4];
            al[m][0] = Al[r * 33 + sp];       al[m][1] = Al[(r + 8) * 33 + sp];
            al[m][2] = Al[r * 33 + sp + 4];   al[m][3] = Al[(r + 8) * 33 + sp + 4];
        }
#pragma unroll
        for (int nt = 0; nt < 4; nt++) {
            const int e0 = (nb + nt) * 8 + g;
            uint32_t bh0 = Bh[e0 * 36 + sp], bh1 = Bh[e0 * 36 + sp + 4];
            uint32_t bl0 = Bl[e0 * 36 + sp], bl1 = Bl[e0 * 36 + sp + 4];
#pragma unroll
            for (int m = 0; m < 2; m++) {
                mma_bf16(acc[m][nt], ah[m], bh0, bh1);
                mma_bf16(acc[m][nt], ah[m], bl0, bl1);
                mma_bf16(acc[m][nt], al[m], bh0, bh1);
            }
        }
    }

    // epilogue: scale by 1/deno and store
    {
        float* op = o + ((size_t)b * SS + s0) * 64;
#pragma unroll
        for (int m = 0; m < 2; m++) {
            const int r = sbw + m * 16 + g;
            const float i0 = iden[r], i1 = iden[r + 8];
#pragma unroll
            for (int nt = 0; nt < 4; nt++) {
                const int e = (nb + nt) * 8 + tig * 2;
                *(float2*)(op + (size_t)r * 64 + e) =
                    make_float2(acc[m][nt][0] * i0, acc[m][nt][1] * i0);
                *(float2*)(op + (size_t)(r + 8) * 64 + e) =
                    make_float2(acc[m][nt][2] * i1, acc[m][nt][3] * i1);
            }
        }
    }
}

// ---------------- launch ----------------
extern "C" void kernel_launch(void* const* d_in, const int* in_sizes, int n_in,
                              void* d_out, int out_size) {
    (void)in_sizes; (void)n_in; (void)out_size;
    const float* q = (const float*)d_in[0];
    const float* k = (const float*)d_in[1];
    const float* v = (const float*)d_in[2];
    float* o = (float*)d_out;

    cudaFuncSetAttribute(phase1_kernel, cudaFuncAttributeMaxDynamicSharedMemorySize, P1_SMEM);
    cudaFuncSetAttribute(phase2_kernel, cudaFuncAttributeMaxDynamicSharedMemorySize, P2_SMEM);

    dim3 g1(SPLIT, BB);
    phase1_kernel<<<g1, 256, P1_SMEM>>>(k, v);

    combine_kernel<<<BB, 256>>>();

    dim3 g2(SS / 128, BB);
    phase2_kernel<<<g2, 256, P2_SMEM>>>(q, o);
}